// round 2
// baseline (speedup 1.0000x reference)
#include <cuda_runtime.h>
#include <math.h>

#define NQ    20
#define DIM   (1u << NQ)
#define BATCH 4
#define LOWC  4   // low-bit values per pass-H tile (coalescing helper)

// ---------------- global scratch (static allocations are allowed) ----------------
static __device__ float2 g_psi[(size_t)BATCH * DIM];   // 33.5 MB state
static __device__ float2 g_u1[NQ][4];                  // fused layer-1 1q gates
static __device__ float2 g_u2[NQ][4];                  // fused layer-2 1q gates (only q10..19 used)
static __device__ float2 g_bond[NQ - 1][16];           // fused XX*YY*ZZ bond gates

// ---------------- small complex helpers ----------------
__device__ __forceinline__ float2 cmul(float2 a, float2 b) {
    return make_float2(a.x * b.x - a.y * b.y, a.x * b.y + a.y * b.x);
}
__device__ __forceinline__ float2 cadd(float2 a, float2 b) {
    return make_float2(a.x + b.x, a.y + b.y);
}

__device__ void mat2mul(const float2* A, const float2* B, float2* C) {
    for (int i = 0; i < 2; i++)
        for (int j = 0; j < 2; j++) {
            float2 s = make_float2(0.f, 0.f);
            for (int k = 0; k < 2; k++) s = cadd(s, cmul(A[i * 2 + k], B[k * 2 + j]));
            C[i * 2 + j] = s;
        }
}
__device__ void mat4mul(const float2* A, const float2* B, float2* C) {
    for (int i = 0; i < 4; i++)
        for (int j = 0; j < 4; j++) {
            float2 s = make_float2(0.f, 0.f);
            for (int k = 0; k < 4; k++) s = cadd(s, cmul(A[i * 4 + k], B[k * 4 + j]));
            C[i * 4 + j] = s;
        }
}

// ---------------- gate precompute (tiny, one warp) ----------------
__global__ void precompute_gates(const float* __restrict__ w) {
    const float WM = 0.6324555320336759f;  // sqrt(2/5)
    int t = threadIdx.x;
    if (t < NQ) {
        for (int layer = 0; layer < 2; layer++) {
            int base = (layer == 0) ? 0 : (6 * NQ - 3);
            float tx = w[base + 3 * t]     * WM;
            float ty = w[base + 3 * t + 1] * WM;
            float tz = w[base + 3 * t + 2] * WM;
            float cx = cosf(0.5f * tx), sx = sinf(0.5f * tx);
            float cy = cosf(0.5f * ty), sy = sinf(0.5f * ty);
            float cz = cosf(0.5f * tz), sz = sinf(0.5f * tz);
            float2 Rx[4] = { {cx,0.f}, {0.f,-sx}, {0.f,-sx}, {cx,0.f} };
            float2 Ry[4] = { {cy,0.f}, {-sy,0.f}, {sy,0.f},  {cy,0.f} };
            float2 Rz[4] = { {cz,-sz}, {0.f,0.f}, {0.f,0.f}, {cz,sz} };
            float2 T[4], U[4];
            mat2mul(Ry, Rx, T);   // Ry * Rx
            mat2mul(Rz, T, U);    // Rz * Ry * Rx  (Rx applied first)
            float2* dst = (layer == 0) ? g_u1[t] : g_u2[t];
            for (int i = 0; i < 4; i++) dst[i] = U[i];
        }
    }
    if (t < NQ - 1) {
        float a = w[3 * NQ + 3 * t]     * WM;
        float b = w[3 * NQ + 3 * t + 1] * WM;
        float c = w[3 * NQ + 3 * t + 2] * WM;
        float ca = cosf(0.5f * a), sa = sinf(0.5f * a);
        float cb = cosf(0.5f * b), sb = sinf(0.5f * b);
        float cc = cosf(0.5f * c), sc = sinf(0.5f * c);
        float2 Rxx[16], Ryy[16], Rzz[16];
        for (int i = 0; i < 16; i++) {
            Rxx[i] = make_float2(0.f, 0.f);
            Ryy[i] = make_float2(0.f, 0.f);
            Rzz[i] = make_float2(0.f, 0.f);
        }
        for (int i = 0; i < 4; i++) {
            Rxx[i * 4 + i] = make_float2(ca, 0.f);
            Ryy[i * 4 + i] = make_float2(cb, 0.f);
        }
        // -i*sa*XX : XX antidiagonal of ones
        Rxx[0 * 4 + 3] = make_float2(0.f, -sa);
        Rxx[1 * 4 + 2] = make_float2(0.f, -sa);
        Rxx[2 * 4 + 1] = make_float2(0.f, -sa);
        Rxx[3 * 4 + 0] = make_float2(0.f, -sa);
        // -i*sb*YY : YY antidiag = (-1, 1, 1, -1)
        Ryy[0 * 4 + 3] = make_float2(0.f,  sb);
        Ryy[1 * 4 + 2] = make_float2(0.f, -sb);
        Ryy[2 * 4 + 1] = make_float2(0.f, -sb);
        Ryy[3 * 4 + 0] = make_float2(0.f,  sb);
        // Rzz = diag(e^{-ic/2}, e^{+ic/2}, e^{+ic/2}, e^{-ic/2})
        Rzz[0]  = make_float2(cc, -sc);
        Rzz[5]  = make_float2(cc,  sc);
        Rzz[10] = make_float2(cc,  sc);
        Rzz[15] = make_float2(cc, -sc);
        float2 T[16], M[16];
        mat4mul(Ryy, Rxx, T);
        mat4mul(Rzz, T, M);
        for (int i = 0; i < 16; i++) g_bond[t][i] = M[i];
    }
}

// ---------------- shared-memory gate helpers ----------------
// Apply 2x2 unitary on bit position rp of an index space with npairs pairs.
__device__ __forceinline__ void apply1q(float2* s, int npairs, int rp,
                                        const float2* __restrict__ U,
                                        int tid, int nth) {
    float2 u00 = U[0], u01 = U[1], u10 = U[2], u11 = U[3];
    for (int p = tid; p < npairs; p += nth) {
        int i0 = ((p >> rp) << (rp + 1)) | (p & ((1 << rp) - 1));
        int i1 = i0 + (1 << rp);
        float2 a0 = s[i0], a1 = s[i1];
        s[i0] = make_float2(u00.x * a0.x - u00.y * a0.y + u01.x * a1.x - u01.y * a1.y,
                            u00.x * a0.y + u00.y * a0.x + u01.x * a1.y + u01.y * a1.x);
        s[i1] = make_float2(u10.x * a0.x - u10.y * a0.y + u11.x * a1.x - u11.y * a1.y,
                            u10.x * a0.y + u10.y * a0.x + u11.x * a1.y + u11.y * a1.x);
    }
}

// Apply 4x4 unitary on bits (pl+1, pl) — pl+1 is the MSB of the 4x4 index.
__device__ __forceinline__ void apply2q(float2* s, int nquads, int pl,
                                        const float2* __restrict__ Mg,
                                        int tid, int nth) {
    float2 m[16];
#pragma unroll
    for (int i = 0; i < 16; i++) m[i] = Mg[i];
    for (int p = tid; p < nquads; p += nth) {
        int lowm = p & ((1 << pl) - 1);
        int i0 = ((p >> pl) << (pl + 2)) | lowm;
        float2 v0 = s[i0];
        float2 v1 = s[i0 | (1 << pl)];
        float2 v2 = s[i0 | (2 << pl)];
        float2 v3 = s[i0 | (3 << pl)];
#pragma unroll
        for (int j = 0; j < 4; j++) {
            float2 m0 = m[j * 4], m1 = m[j * 4 + 1], m2 = m[j * 4 + 2], m3 = m[j * 4 + 3];
            float rr = m0.x * v0.x - m0.y * v0.y + m1.x * v1.x - m1.y * v1.y
                     + m2.x * v2.x - m2.y * v2.y + m3.x * v3.x - m3.y * v3.y;
            float ri = m0.x * v0.y + m0.y * v0.x + m1.x * v1.y + m1.y * v1.x
                     + m2.x * v2.y + m2.y * v2.x + m3.x * v3.y + m3.y * v3.x;
            s[i0 | (j << pl)] = make_float2(rr, ri);
        }
    }
}

// ---------------- Pass H: bits 10..19 (wires 0..9) ----------------
// Tile: LOWC consecutive low values x all 1024 high values (stride 1024).
// smem layout: s[(h << 2) | l]  — so a gate on relative high bit rp acts at
// combined bit (rp + 2); the two low-carry bits just ride along.
__global__ void pass_high(const float* __restrict__ x) {
    __shared__ float2 s[1024 * LOWC];   // 32 KB
    const int b    = blockIdx.y;
    const int low0 = blockIdx.x * LOWC;
    const int tid  = threadIdx.x;
    const float* xb = x + (size_t)b * DIM;

    for (int e = tid; e < 1024 * LOWC; e += blockDim.x) {
        int l = e & (LOWC - 1), h = e >> 2;
        s[e] = make_float2(xb[h * 1024 + low0 + l], 0.f);
    }
    __syncthreads();

    // Layer-1 1q gates on wires 0..9 (rel bit 9-q, combined bit 9-q+2)
    for (int q = 0; q < 10; q++) {
        apply1q(s, 2048, (9 - q) + 2, g_u1[q], tid, blockDim.x);
        __syncthreads();
    }
    // Bonds 0..8 in order (wires (q,q+1) -> rel bits (9-q, 8-q), combined pl = (8-q)+2)
    for (int q = 0; q < 9; q++) {
        apply2q(s, 1024, (8 - q) + 2, g_bond[q], tid, blockDim.x);
        __syncthreads();
    }

    float2* pb = g_psi + (size_t)b * DIM;
    for (int e = tid; e < 1024 * LOWC; e += blockDim.x) {
        int l = e & (LOWC - 1), h = e >> 2;
        pb[h * 1024 + low0 + l] = s[e];
    }
}

// ---------------- Pass L: bits 0..10 (wires 9..19), contiguous 2048-amp tiles ----------------
__global__ void pass_low() {
    __shared__ float2 s[2048];   // 16 KB
    const int b = blockIdx.y;
    const size_t base = (size_t)b * DIM + (size_t)blockIdx.x * 2048;
    const int tid = threadIdx.x;

    for (int e = tid; e < 2048; e += blockDim.x) s[e] = g_psi[base + e];
    __syncthreads();

    // Layer-1 1q gates on wires 10..19 (bit 19-q)
    for (int q = 10; q < 20; q++) {
        apply1q(s, 1024, 19 - q, g_u1[q], tid, blockDim.x);
        __syncthreads();
    }
    // Bond 9 (bits 10,9) then bonds 10..18 (bits 9..0), in order: pl = 18-q
    for (int q = 9; q < 19; q++) {
        apply2q(s, 512, 18 - q, g_bond[q], tid, blockDim.x);
        __syncthreads();
    }
    // Layer-2 1q gates on wires 10..19 ONLY.
    // (Layer-2 gates on wires 0..9 act purely on the traced index after the last
    //  coupling gate -> rdm-invariant -> skipped.)
    for (int q = 10; q < 20; q++) {
        apply1q(s, 1024, 19 - q, g_u2[q], tid, blockDim.x);
        __syncthreads();
    }

    for (int e = tid; e < 2048; e += blockDim.x) g_psi[base + e] = s[e];
}

// ---------------- rdm GEMM: C[a,c] = sum_t P[t,a] * conj(P[t,c]) ----------------
// P = psi[b] viewed as [1024 (t = bits 10..19)][1024 (a = bits 0..9)].
// Hermitian: only tiles ta <= tc; mirror with conjugate.
__global__ void rdm_gemm(float* __restrict__ out) {
    __shared__ float2 Sa[16][64];
    __shared__ float2 Sc[16][64];

    // linear block id -> (ta, tc), ta <= tc over a 16x16 tile grid (136 blocks)
    int lin = blockIdx.x;
    int ta = 0, rem = lin;
    while (rem >= 16 - ta) { rem -= 16 - ta; ta++; }
    int tc = ta + rem;

    const int b = blockIdx.y;
    const float2* P = g_psi + (size_t)b * DIM;
    const int a0 = ta * 64, c0 = tc * 64;
    const int tid = threadIdx.x;
    const int tx = tid & 15;        // a-fragment lane
    const int ty = tid >> 4;        // c-fragment lane

    float accr[4][4] = {};
    float acci[4][4] = {};

    for (int k0 = 0; k0 < 1024; k0 += 16) {
        for (int e = tid; e < 1024; e += 256) {
            int i = e & 63, kk = e >> 6;
            Sa[kk][i] = P[(size_t)(k0 + kk) * 1024 + a0 + i];
            Sc[kk][i] = P[(size_t)(k0 + kk) * 1024 + c0 + i];
        }
        __syncthreads();
#pragma unroll
        for (int kk = 0; kk < 16; kk++) {
            float2 af[4], cf[4];
#pragma unroll
            for (int u = 0; u < 4; u++) af[u] = Sa[kk][tx + 16 * u];
#pragma unroll
            for (int v = 0; v < 4; v++) cf[v] = Sc[kk][ty + 16 * v];
#pragma unroll
            for (int u = 0; u < 4; u++)
#pragma unroll
                for (int v = 0; v < 4; v++) {
                    accr[u][v] += af[u].x * cf[v].x + af[u].y * cf[v].y;
                    acci[u][v] += af[u].y * cf[v].x - af[u].x * cf[v].y;
                }
        }
        __syncthreads();
    }

#pragma unroll
    for (int u = 0; u < 4; u++)
#pragma unroll
        for (int v = 0; v < 4; v++) {
            int a = a0 + tx + 16 * u;
            int c = c0 + ty + 16 * v;
            size_t o1 = ((size_t)(b * 1024 + a) * 1024 + c) * 2;
            out[o1]     = accr[u][v];
            out[o1 + 1] = acci[u][v];
            if (ta != tc) {
                size_t o2 = ((size_t)(b * 1024 + c) * 1024 + a) * 2;
                out[o2]     = accr[u][v];
                out[o2 + 1] = -acci[u][v];
            }
        }
}

// ---------------- launch ----------------
extern "C" void kernel_launch(void* const* d_in, const int* in_sizes, int n_in,
                              void* d_out, int out_size) {
    const float* x = (const float*)d_in[0];       // [4, 1, 2^20] float32
    const float* w = (const float*)d_in[1];       // [177] float32
    float* out = (float*)d_out;                   // [4, 1024, 1024, 2] float32

    precompute_gates<<<1, 32>>>(w);
    pass_high<<<dim3(1024 / LOWC, BATCH), 256>>>(x);
    pass_low<<<dim3(512, BATCH), 256>>>();
    rdm_gemm<<<dim3(136, BATCH), 256>>>(out);
}

// round 3
// speedup vs baseline: 2.0963x; 2.0963x over previous
#include <cuda_runtime.h>
#include <cuda_bf16.h>
#include <math.h>
#include <stdint.h>

#define NQ    20
#define DIM   (1u << NQ)
#define BATCH 4
#define LOWC  4

// ---------------- global scratch ----------------
static __device__ float2 g_psi[(size_t)BATCH * DIM];   // intermediate state (pass H -> pass L)
static __device__ uint2  g_pk [(size_t)BATCH * DIM];   // packed bf16 (reHi,reLo | imHi,imLo)
static __device__ float2 g_fused[NQ - 1][16];          // 19 fully-fused 4x4 gates

// ---------------- complex helpers ----------------
__device__ __forceinline__ float2 cmul(float2 a, float2 b) {
    return make_float2(a.x * b.x - a.y * b.y, a.x * b.y + a.y * b.x);
}
__device__ __forceinline__ float2 cadd(float2 a, float2 b) {
    return make_float2(a.x + b.x, a.y + b.y);
}
__device__ void mat2mul(const float2* A, const float2* B, float2* C) {
    for (int i = 0; i < 2; i++)
        for (int j = 0; j < 2; j++) {
            float2 s = make_float2(0.f, 0.f);
            for (int k = 0; k < 2; k++) s = cadd(s, cmul(A[i * 2 + k], B[k * 2 + j]));
            C[i * 2 + j] = s;
        }
}
__device__ void mat4mul(const float2* A, const float2* B, float2* C) {
    for (int i = 0; i < 4; i++)
        for (int j = 0; j < 4; j++) {
            float2 s = make_float2(0.f, 0.f);
            for (int k = 0; k < 4; k++) s = cadd(s, cmul(A[i * 4 + k], B[k * 4 + j]));
            C[i * 4 + j] = s;
        }
}
// kron: index = (wire q bit as MSB, wire q+1 bit as LSB)
__device__ void kron22(const float2* A, const float2* B, float2* C) {
    for (int i2 = 0; i2 < 2; i2++)
        for (int i1 = 0; i1 < 2; i1++)
            for (int j2 = 0; j2 < 2; j2++)
                for (int j1 = 0; j1 < 2; j1++)
                    C[(i2 * 2 + i1) * 4 + (j2 * 2 + j1)] = cmul(A[i2 * 2 + j2], B[i1 * 2 + j1]);
}

// ---------------- gate precompute: fuse whole circuit into 19 4x4 gates ----------------
__global__ void precompute_gates(const float* __restrict__ w) {
    const float WM = 0.6324555320336759f;  // sqrt(2/5)
    __shared__ float2 U1[NQ][4];
    __shared__ float2 U2[NQ][4];
    int t = threadIdx.x;
    if (t < NQ) {
        for (int layer = 0; layer < 2; layer++) {
            int base = (layer == 0) ? 0 : (6 * NQ - 3);
            float tx = w[base + 3 * t]     * WM;
            float ty = w[base + 3 * t + 1] * WM;
            float tz = w[base + 3 * t + 2] * WM;
            float cx = cosf(0.5f * tx), sx = sinf(0.5f * tx);
            float cy = cosf(0.5f * ty), sy = sinf(0.5f * ty);
            float cz = cosf(0.5f * tz), sz = sinf(0.5f * tz);
            float2 Rx[4] = { {cx,0.f}, {0.f,-sx}, {0.f,-sx}, {cx,0.f} };
            float2 Ry[4] = { {cy,0.f}, {-sy,0.f}, {sy,0.f},  {cy,0.f} };
            float2 Rz[4] = { {cz,-sz}, {0.f,0.f}, {0.f,0.f}, {cz,sz} };
            float2 T[4], U[4];
            mat2mul(Ry, Rx, T);
            mat2mul(Rz, T, U);   // Rz*Ry*Rx (Rx first)
            float2* dst = (layer == 0) ? U1[t] : U2[t];
            for (int i = 0; i < 4; i++) dst[i] = U[i];
        }
    }
    __syncthreads();
    if (t < NQ - 1) {
        float a = w[3 * NQ + 3 * t]     * WM;
        float b = w[3 * NQ + 3 * t + 1] * WM;
        float c = w[3 * NQ + 3 * t + 2] * WM;
        float ca = cosf(0.5f * a), sa = sinf(0.5f * a);
        float cb = cosf(0.5f * b), sb = sinf(0.5f * b);
        float cc = cosf(0.5f * c), sc = sinf(0.5f * c);
        float2 Rxx[16], Ryy[16], Rzz[16];
        for (int i = 0; i < 16; i++) {
            Rxx[i] = make_float2(0.f, 0.f);
            Ryy[i] = make_float2(0.f, 0.f);
            Rzz[i] = make_float2(0.f, 0.f);
        }
        for (int i = 0; i < 4; i++) {
            Rxx[i * 4 + i] = make_float2(ca, 0.f);
            Ryy[i * 4 + i] = make_float2(cb, 0.f);
        }
        Rxx[3]  = make_float2(0.f, -sa);
        Rxx[6]  = make_float2(0.f, -sa);
        Rxx[9]  = make_float2(0.f, -sa);
        Rxx[12] = make_float2(0.f, -sa);
        Ryy[3]  = make_float2(0.f,  sb);
        Ryy[6]  = make_float2(0.f, -sb);
        Ryy[9]  = make_float2(0.f, -sb);
        Ryy[12] = make_float2(0.f,  sb);
        Rzz[0]  = make_float2(cc, -sc);
        Rzz[5]  = make_float2(cc,  sc);
        Rzz[10] = make_float2(cc,  sc);
        Rzz[15] = make_float2(cc, -sc);
        float2 T[16], Bq[16];
        mat4mul(Ryy, Rxx, T);
        mat4mul(Rzz, T, Bq);     // fused bond: Rzz*Ryy*Rxx

        float2 I2m[4] = { {1.f,0.f},{0.f,0.f},{0.f,0.f},{1.f,0.f} };
        float2 R[16], G[16];
        // right-absorb layer-1 gates (applied before this bond)
        if (t == 0) kron22(U1[0], U1[1], R);
        else        kron22(I2m, U1[t + 1], R);
        mat4mul(Bq, R, G);
        // left-absorb layer-2 gates on wires >= 10 (layer-2 on wires 0..9 is
        // trace-invariant and skipped)
        if (t >= 10) {
            float2 L[16], G2[16];
            if (t == 18) kron22(U2[18], U2[19], L);
            else         kron22(U2[t], I2m, L);
            mat4mul(L, G, G2);
            for (int i = 0; i < 16; i++) G[i] = G2[i];
        }
        for (int i = 0; i < 16; i++) g_fused[t][i] = G[i];
    }
}

// ---------------- 2q gate on shared tile ----------------
__device__ __forceinline__ void apply2q(float2* s, int nquads, int pl,
                                        const float2* __restrict__ Mg,
                                        int tid, int nth) {
    float2 m[16];
#pragma unroll
    for (int i = 0; i < 16; i++) m[i] = Mg[i];
    for (int p = tid; p < nquads; p += nth) {
        int lowm = p & ((1 << pl) - 1);
        int i0 = ((p >> pl) << (pl + 2)) | lowm;
        float2 v0 = s[i0];
        float2 v1 = s[i0 | (1 << pl)];
        float2 v2 = s[i0 | (2 << pl)];
        float2 v3 = s[i0 | (3 << pl)];
#pragma unroll
        for (int j = 0; j < 4; j++) {
            float2 m0 = m[j * 4], m1 = m[j * 4 + 1], m2 = m[j * 4 + 2], m3 = m[j * 4 + 3];
            float rr = m0.x * v0.x - m0.y * v0.y + m1.x * v1.x - m1.y * v1.y
                     + m2.x * v2.x - m2.y * v2.y + m3.x * v3.x - m3.y * v3.y;
            float ri = m0.x * v0.y + m0.y * v0.x + m1.x * v1.y + m1.y * v1.x
                     + m2.x * v2.y + m2.y * v2.x + m3.x * v3.y + m3.y * v3.x;
            s[i0 | (j << pl)] = make_float2(rr, ri);
        }
    }
}

// ---------------- Pass H: bonds 0..8 (bits 19..10) ----------------
__global__ void pass_high(const float* __restrict__ x) {
    __shared__ float2 s[1024 * LOWC];
    const int b    = blockIdx.y;
    const int low0 = blockIdx.x * LOWC;
    const int tid  = threadIdx.x;
    const float* xb = x + (size_t)b * DIM;

    for (int e = tid; e < 1024 * LOWC; e += blockDim.x) {
        int l = e & (LOWC - 1), h = e >> 2;
        s[e] = make_float2(xb[h * 1024 + low0 + l], 0.f);
    }
    __syncthreads();
    for (int q = 0; q < 9; q++) {
        apply2q(s, 1024, (8 - q) + 2, g_fused[q], tid, blockDim.x);
        __syncthreads();
    }
    float2* pb = g_psi + (size_t)b * DIM;
    for (int e = tid; e < 1024 * LOWC; e += blockDim.x) {
        int l = e & (LOWC - 1), h = e >> 2;
        pb[h * 1024 + low0 + l] = s[e];
    }
}

// ---------------- bf16 split pack ----------------
__device__ __forceinline__ uint32_t pack_split(float v) {
    __nv_bfloat16 h = __float2bfloat16(v);
    float hf = __bfloat162float(h);
    __nv_bfloat16 l = __float2bfloat16(v - hf);
    unsigned short hs = *reinterpret_cast<unsigned short*>(&h);
    unsigned short ls = *reinterpret_cast<unsigned short*>(&l);
    return ((uint32_t)ls << 16) | (uint32_t)hs;
}

// ---------------- Pass L: bonds 9..18 (bits 10..0); emit packed bf16 ----------------
__global__ void pass_low() {
    __shared__ float2 s[2048];
    const int b = blockIdx.y;
    const size_t base = (size_t)b * DIM + (size_t)blockIdx.x * 2048;
    const int tid = threadIdx.x;

    for (int e = tid; e < 2048; e += blockDim.x) s[e] = g_psi[base + e];
    __syncthreads();
    for (int q = 9; q < 19; q++) {
        apply2q(s, 512, 18 - q, g_fused[q], tid, blockDim.x);
        __syncthreads();
    }
    for (int e = tid; e < 2048; e += blockDim.x) {
        float2 v = s[e];
        g_pk[base + e] = make_uint2(pack_split(v.x), pack_split(v.y));
    }
}

// ---------------- rdm GEMM via bf16 tensor cores + mantissa split ----------------
// C[a,c] = sum_t P[t,a] * conj(P[t,c]); Hermitian: tiles ta <= tc, mirrored.
// Block: 64(a) x 64(c), 8 warps as 2(m) x 4(n). Warp: 2 m-tiles(16) x 2 n-tiles(8).
#define SAS 18   // smem k-stride in bf16 elements (16 + 2 pad)

__device__ __forceinline__ void mma_bf16(float* d, uint32_t a0, uint32_t a1,
                                         uint32_t a2, uint32_t a3,
                                         uint32_t b0, uint32_t b1) {
    asm volatile(
        "mma.sync.aligned.m16n8k16.row.col.f32.bf16.bf16.f32 "
        "{%0,%1,%2,%3},{%4,%5,%6,%7},{%8,%9},{%0,%1,%2,%3};"
        : "+f"(d[0]), "+f"(d[1]), "+f"(d[2]), "+f"(d[3])
        : "r"(a0), "r"(a1), "r"(a2), "r"(a3), "r"(b0), "r"(b1));
}

__global__ void __launch_bounds__(256) rdm_gemm(float* __restrict__ out) {
    // A arrays: 0=reHi 1=reLo 2=imHi 3=imLo
    // B arrays: 0=reHi 1=reLo 2=imHi 3=imLo 4=-imHi 5=-imLo
    __shared__ unsigned short sA[4][64 * SAS];
    __shared__ unsigned short sB[6][64 * SAS];

    int lin = blockIdx.x;
    int ta = 0, rem = lin;
    while (rem >= 16 - ta) { rem -= 16 - ta; ta++; }
    int tc = ta + rem;

    const int b = blockIdx.y;
    const uint2* P = g_pk + (size_t)b * DIM;
    const int a0b = ta * 64, c0b = tc * 64;
    const int tid  = threadIdx.x;
    const int wid  = tid >> 5;
    const int lane = tid & 31;
    const int g    = lane >> 2;
    const int t4   = lane & 3;
    const int warpM = wid & 1;         // 0..1 -> a offset 0/32
    const int warpN = wid >> 1;        // 0..3 -> c offset 0/16/32/48

    float accR[2][2][4] = {};
    float accI[2][2][4] = {};

    for (int k0 = 0; k0 < 1024; k0 += 16) {
        // ---- stage tiles ----
#pragma unroll
        for (int e = tid; e < 1024; e += 256) {
            int i = e & 63, kk = e >> 6;
            uint2 va = P[(size_t)(k0 + kk) * 1024 + a0b + i];
            int o = i * SAS + kk;
            sA[0][o] = (unsigned short)(va.x & 0xffff);
            sA[1][o] = (unsigned short)(va.x >> 16);
            sA[2][o] = (unsigned short)(va.y & 0xffff);
            sA[3][o] = (unsigned short)(va.y >> 16);
            uint2 vc = P[(size_t)(k0 + kk) * 1024 + c0b + i];
            sB[0][o] = (unsigned short)(vc.x & 0xffff);
            sB[1][o] = (unsigned short)(vc.x >> 16);
            sB[2][o] = (unsigned short)(vc.y & 0xffff);
            sB[3][o] = (unsigned short)(vc.y >> 16);
            sB[4][o] = (unsigned short)((vc.y & 0xffff) ^ 0x8000);
            sB[5][o] = (unsigned short)((vc.y >> 16) ^ 0x8000);
        }
        __syncthreads();

        // ---- load A fragments (2 m-tiles x 4 arrays) ----
        uint32_t Af[2][4][4];
#pragma unroll
        for (int mi = 0; mi < 2; mi++) {
            int r0 = (warpM * 32 + mi * 16 + g) * SAS;
            int r1 = r0 + 8 * SAS;
#pragma unroll
            for (int ar = 0; ar < 4; ar++) {
                Af[mi][ar][0] = *(const uint32_t*)&sA[ar][r0 + 2 * t4];
                Af[mi][ar][1] = *(const uint32_t*)&sA[ar][r1 + 2 * t4];
                Af[mi][ar][2] = *(const uint32_t*)&sA[ar][r0 + 2 * t4 + 8];
                Af[mi][ar][3] = *(const uint32_t*)&sA[ar][r1 + 2 * t4 + 8];
            }
        }

#pragma unroll
        for (int ni = 0; ni < 2; ni++) {
            uint32_t Bf[6][2];
            int col = (warpN * 16 + ni * 8 + g) * SAS;
#pragma unroll
            for (int ar = 0; ar < 6; ar++) {
                Bf[ar][0] = *(const uint32_t*)&sB[ar][col + 2 * t4];
                Bf[ar][1] = *(const uint32_t*)&sB[ar][col + 2 * t4 + 8];
            }
#pragma unroll
            for (int mi = 0; mi < 2; mi++) {
                float* dR = accR[mi][ni];
                float* dI = accI[mi][ni];
                // Real: Ar*Br + Ai*Bi (hi*hi + hi*lo + lo*hi each)
                mma_bf16(dR, Af[mi][0][0], Af[mi][0][1], Af[mi][0][2], Af[mi][0][3], Bf[0][0], Bf[0][1]); // rHi*rHi
                mma_bf16(dR, Af[mi][0][0], Af[mi][0][1], Af[mi][0][2], Af[mi][0][3], Bf[1][0], Bf[1][1]); // rHi*rLo
                mma_bf16(dR, Af[mi][1][0], Af[mi][1][1], Af[mi][1][2], Af[mi][1][3], Bf[0][0], Bf[0][1]); // rLo*rHi
                mma_bf16(dR, Af[mi][2][0], Af[mi][2][1], Af[mi][2][2], Af[mi][2][3], Bf[2][0], Bf[2][1]); // iHi*iHi
                mma_bf16(dR, Af[mi][2][0], Af[mi][2][1], Af[mi][2][2], Af[mi][2][3], Bf[3][0], Bf[3][1]); // iHi*iLo
                mma_bf16(dR, Af[mi][3][0], Af[mi][3][1], Af[mi][3][2], Af[mi][3][3], Bf[2][0], Bf[2][1]); // iLo*iHi
                // Imag: Ai*Br + Ar*(-Bi)
                mma_bf16(dI, Af[mi][2][0], Af[mi][2][1], Af[mi][2][2], Af[mi][2][3], Bf[0][0], Bf[0][1]); // iHi*rHi
                mma_bf16(dI, Af[mi][2][0], Af[mi][2][1], Af[mi][2][2], Af[mi][2][3], Bf[1][0], Bf[1][1]); // iHi*rLo
                mma_bf16(dI, Af[mi][3][0], Af[mi][3][1], Af[mi][3][2], Af[mi][3][3], Bf[0][0], Bf[0][1]); // iLo*rHi
                mma_bf16(dI, Af[mi][0][0], Af[mi][0][1], Af[mi][0][2], Af[mi][0][3], Bf[4][0], Bf[4][1]); // rHi*-iHi
                mma_bf16(dI, Af[mi][0][0], Af[mi][0][1], Af[mi][0][2], Af[mi][0][3], Bf[5][0], Bf[5][1]); // rHi*-iLo
                mma_bf16(dI, Af[mi][1][0], Af[mi][1][1], Af[mi][1][2], Af[mi][1][3], Bf[4][0], Bf[4][1]); // rLo*-iHi
            }
        }
        __syncthreads();
    }

    // ---- epilogue ----
#pragma unroll
    for (int mi = 0; mi < 2; mi++)
#pragma unroll
        for (int ni = 0; ni < 2; ni++)
#pragma unroll
            for (int r = 0; r < 4; r++) {
                int a = a0b + warpM * 32 + mi * 16 + g + ((r & 2) ? 8 : 0);
                int c = c0b + warpN * 16 + ni * 8 + 2 * t4 + (r & 1);
                float vr = accR[mi][ni][r];
                float vi = accI[mi][ni][r];
                size_t o1 = ((size_t)(b * 1024 + a) * 1024 + c) * 2;
                out[o1]     = vr;
                out[o1 + 1] = vi;
                if (ta != tc) {
                    size_t o2 = ((size_t)(b * 1024 + c) * 1024 + a) * 2;
                    out[o2]     = vr;
                    out[o2 + 1] = -vi;
                }
            }
}

// ---------------- launch ----------------
extern "C" void kernel_launch(void* const* d_in, const int* in_sizes, int n_in,
                              void* d_out, int out_size) {
    const float* x = (const float*)d_in[0];
    const float* w = (const float*)d_in[1];
    float* out = (float*)d_out;

    precompute_gates<<<1, 32>>>(w);
    pass_high<<<dim3(1024 / LOWC, BATCH), 256>>>(x);
    pass_low<<<dim3(512, BATCH), 256>>>();
    rdm_gemm<<<dim3(136, BATCH), 256>>>(out);
}

// round 4
// speedup vs baseline: 2.5637x; 1.2229x over previous
#include <cuda_runtime.h>
#include <cuda_bf16.h>
#include <math.h>
#include <stdint.h>

#define NQ    20
#define DIM   (1u << NQ)
#define BATCH 4
#define LOWC  4

// ---------------- global scratch ----------------
static __device__ float2 g_psi[(size_t)BATCH * DIM];   // intermediate state
static __device__ uint2  g_pk [(size_t)BATCH * DIM];   // packed bf16 (reHi,reLo | imHi,imLo)
static __device__ float2 g_fused[NQ - 1][16];          // 19 fully-fused 4x4 gates

// ---------------- complex helpers ----------------
__device__ __forceinline__ float2 cmul(float2 a, float2 b) {
    return make_float2(a.x * b.x - a.y * b.y, a.x * b.y + a.y * b.x);
}
__device__ __forceinline__ float2 cadd(float2 a, float2 b) {
    return make_float2(a.x + b.x, a.y + b.y);
}
__device__ void mat2mul(const float2* A, const float2* B, float2* C) {
    for (int i = 0; i < 2; i++)
        for (int j = 0; j < 2; j++) {
            float2 s = make_float2(0.f, 0.f);
            for (int k = 0; k < 2; k++) s = cadd(s, cmul(A[i * 2 + k], B[k * 2 + j]));
            C[i * 2 + j] = s;
        }
}
__device__ void mat4mul(const float2* A, const float2* B, float2* C) {
    for (int i = 0; i < 4; i++)
        for (int j = 0; j < 4; j++) {
            float2 s = make_float2(0.f, 0.f);
            for (int k = 0; k < 4; k++) s = cadd(s, cmul(A[i * 4 + k], B[k * 4 + j]));
            C[i * 4 + j] = s;
        }
}
__device__ void kron22(const float2* A, const float2* B, float2* C) {
    for (int i2 = 0; i2 < 2; i2++)
        for (int i1 = 0; i1 < 2; i1++)
            for (int j2 = 0; j2 < 2; j2++)
                for (int j1 = 0; j1 < 2; j1++)
                    C[(i2 * 2 + i1) * 4 + (j2 * 2 + j1)] = cmul(A[i2 * 2 + j2], B[i1 * 2 + j1]);
}

// ---------------- gate precompute ----------------
__global__ void precompute_gates(const float* __restrict__ w) {
    const float WM = 0.6324555320336759f;  // sqrt(2/5)
    __shared__ float2 U1[NQ][4];
    __shared__ float2 U2[NQ][4];
    int t = threadIdx.x;
    if (t < NQ) {
        for (int layer = 0; layer < 2; layer++) {
            int base = (layer == 0) ? 0 : (6 * NQ - 3);
            float tx = w[base + 3 * t]     * WM;
            float ty = w[base + 3 * t + 1] * WM;
            float tz = w[base + 3 * t + 2] * WM;
            float cx = cosf(0.5f * tx), sx = sinf(0.5f * tx);
            float cy = cosf(0.5f * ty), sy = sinf(0.5f * ty);
            float cz = cosf(0.5f * tz), sz = sinf(0.5f * tz);
            float2 Rx[4] = { {cx,0.f}, {0.f,-sx}, {0.f,-sx}, {cx,0.f} };
            float2 Ry[4] = { {cy,0.f}, {-sy,0.f}, {sy,0.f},  {cy,0.f} };
            float2 Rz[4] = { {cz,-sz}, {0.f,0.f}, {0.f,0.f}, {cz,sz} };
            float2 T[4], U[4];
            mat2mul(Ry, Rx, T);
            mat2mul(Rz, T, U);
            float2* dst = (layer == 0) ? U1[t] : U2[t];
            for (int i = 0; i < 4; i++) dst[i] = U[i];
        }
    }
    __syncthreads();
    if (t < NQ - 1) {
        float a = w[3 * NQ + 3 * t]     * WM;
        float b = w[3 * NQ + 3 * t + 1] * WM;
        float c = w[3 * NQ + 3 * t + 2] * WM;
        float ca = cosf(0.5f * a), sa = sinf(0.5f * a);
        float cb = cosf(0.5f * b), sb = sinf(0.5f * b);
        float cc = cosf(0.5f * c), sc = sinf(0.5f * c);
        float2 Rxx[16], Ryy[16], Rzz[16];
        for (int i = 0; i < 16; i++) {
            Rxx[i] = make_float2(0.f, 0.f);
            Ryy[i] = make_float2(0.f, 0.f);
            Rzz[i] = make_float2(0.f, 0.f);
        }
        for (int i = 0; i < 4; i++) {
            Rxx[i * 4 + i] = make_float2(ca, 0.f);
            Ryy[i * 4 + i] = make_float2(cb, 0.f);
        }
        Rxx[3]  = make_float2(0.f, -sa);
        Rxx[6]  = make_float2(0.f, -sa);
        Rxx[9]  = make_float2(0.f, -sa);
        Rxx[12] = make_float2(0.f, -sa);
        Ryy[3]  = make_float2(0.f,  sb);
        Ryy[6]  = make_float2(0.f, -sb);
        Ryy[9]  = make_float2(0.f, -sb);
        Ryy[12] = make_float2(0.f,  sb);
        Rzz[0]  = make_float2(cc, -sc);
        Rzz[5]  = make_float2(cc,  sc);
        Rzz[10] = make_float2(cc,  sc);
        Rzz[15] = make_float2(cc, -sc);
        float2 T[16], Bq[16];
        mat4mul(Ryy, Rxx, T);
        mat4mul(Rzz, T, Bq);

        float2 I2m[4] = { {1.f,0.f},{0.f,0.f},{0.f,0.f},{1.f,0.f} };
        float2 R[16], G[16];
        if (t == 0) kron22(U1[0], U1[1], R);
        else        kron22(I2m, U1[t + 1], R);
        mat4mul(Bq, R, G);
        if (t >= 10) {
            float2 L[16], G2[16];
            if (t == 18) kron22(U2[18], U2[19], L);
            else         kron22(U2[t], I2m, L);
            mat4mul(L, G, G2);
            for (int i = 0; i < 16; i++) G[i] = G2[i];
        }
        for (int i = 0; i < 16; i++) g_fused[t][i] = G[i];
    }
}

// ---------------- 2q gate on shared tile ----------------
__device__ __forceinline__ void apply2q(float2* s, int nquads, int pl,
                                        const float2* __restrict__ Mg,
                                        int tid, int nth) {
    float2 m[16];
#pragma unroll
    for (int i = 0; i < 16; i++) m[i] = Mg[i];
    for (int p = tid; p < nquads; p += nth) {
        int lowm = p & ((1 << pl) - 1);
        int i0 = ((p >> pl) << (pl + 2)) | lowm;
        float2 v0 = s[i0];
        float2 v1 = s[i0 | (1 << pl)];
        float2 v2 = s[i0 | (2 << pl)];
        float2 v3 = s[i0 | (3 << pl)];
#pragma unroll
        for (int j = 0; j < 4; j++) {
            float2 m0 = m[j * 4], m1 = m[j * 4 + 1], m2 = m[j * 4 + 2], m3 = m[j * 4 + 3];
            float rr = m0.x * v0.x - m0.y * v0.y + m1.x * v1.x - m1.y * v1.y
                     + m2.x * v2.x - m2.y * v2.y + m3.x * v3.x - m3.y * v3.y;
            float ri = m0.x * v0.y + m0.y * v0.x + m1.x * v1.y + m1.y * v1.x
                     + m2.x * v2.y + m2.y * v2.x + m3.x * v3.y + m3.y * v3.x;
            s[i0 | (j << pl)] = make_float2(rr, ri);
        }
    }
}

// ---------------- Pass H ----------------
__global__ void pass_high(const float* __restrict__ x) {
    __shared__ float2 s[1024 * LOWC];
    const int b    = blockIdx.y;
    const int low0 = blockIdx.x * LOWC;
    const int tid  = threadIdx.x;
    const float* xb = x + (size_t)b * DIM;

    for (int e = tid; e < 1024 * LOWC; e += blockDim.x) {
        int l = e & (LOWC - 1), h = e >> 2;
        s[e] = make_float2(xb[h * 1024 + low0 + l], 0.f);
    }
    __syncthreads();
    for (int q = 0; q < 9; q++) {
        apply2q(s, 1024, (8 - q) + 2, g_fused[q], tid, blockDim.x);
        __syncthreads();
    }
    float2* pb = g_psi + (size_t)b * DIM;
    for (int e = tid; e < 1024 * LOWC; e += blockDim.x) {
        int l = e & (LOWC - 1), h = e >> 2;
        pb[h * 1024 + low0 + l] = s[e];
    }
}

// ---------------- bf16 split pack ----------------
__device__ __forceinline__ uint32_t pack_split(float v) {
    __nv_bfloat16 h = __float2bfloat16(v);
    float hf = __bfloat162float(h);
    __nv_bfloat16 l = __float2bfloat16(v - hf);
    unsigned short hs = *reinterpret_cast<unsigned short*>(&h);
    unsigned short ls = *reinterpret_cast<unsigned short*>(&l);
    return ((uint32_t)ls << 16) | (uint32_t)hs;
}

// ---------------- Pass L ----------------
__global__ void pass_low() {
    __shared__ float2 s[2048];
    const int b = blockIdx.y;
    const size_t base = (size_t)b * DIM + (size_t)blockIdx.x * 2048;
    const int tid = threadIdx.x;

    for (int e = tid; e < 2048; e += blockDim.x) s[e] = g_psi[base + e];
    __syncthreads();
    for (int q = 9; q < 19; q++) {
        apply2q(s, 512, 18 - q, g_fused[q], tid, blockDim.x);
        __syncthreads();
    }
    for (int e = tid; e < 2048; e += blockDim.x) {
        float2 v = s[e];
        g_pk[base + e] = make_uint2(pack_split(v.x), pack_split(v.y));
    }
}

// ---------------- rdm GEMM v3 ----------------
// C[a,c] = sum_t P[t,a]*conj(P[t,c]).  Block tile 64(a) x 128(c), 8 warps of
// 32x32.  k-major smem: sA[16][66] uint2, sB[16][130] uint2 (pad ≡2 mod 16 ->
// conflict-free per half-warp phase), double-buffered, register prefetch.
// Hi/lo bf16 planes unpacked from packed uint2 via PRMT at fragment build.
#define ASTR 66
#define BSTR 130
#define A_BUF (16 * ASTR)
#define B_BUF (16 * BSTR)
#define GEMM_SMEM ((2 * (A_BUF + B_BUF)) * 8)

__device__ __forceinline__ void mma_bf16(float* d, uint32_t a0, uint32_t a1,
                                         uint32_t a2, uint32_t a3,
                                         uint32_t b0, uint32_t b1) {
    asm volatile(
        "mma.sync.aligned.m16n8k16.row.col.f32.bf16.bf16.f32 "
        "{%0,%1,%2,%3},{%4,%5,%6,%7},{%8,%9},{%0,%1,%2,%3};"
        : "+f"(d[0]), "+f"(d[1]), "+f"(d[2]), "+f"(d[3])
        : "r"(a0), "r"(a1), "r"(a2), "r"(a3), "r"(b0), "r"(b1));
}

__global__ void __launch_bounds__(256) rdm_gemm(float* __restrict__ out) {
    extern __shared__ uint2 sm[];
    uint2* smA = sm;                       // [2][16][ASTR]
    uint2* smB = sm + 2 * A_BUF;           // [2][16][BSTR]

    // decode linear block -> (col tile tcc of 128, row tile ta of 64), keep ta<=2tcc+1
    int tcc = 0, rem = blockIdx.x;
    while (rem >= 2 * tcc + 2) { rem -= 2 * tcc + 2; tcc++; }
    int ta = rem;

    const int b = blockIdx.y;
    const uint2* P = g_pk + (size_t)b * DIM;
    const int a0b = ta * 64, c0b = tcc * 128;
    const int tid  = threadIdx.x;
    const int wid  = tid >> 5;
    const int lane = tid & 31;
    const int g    = lane >> 2;
    const int t4   = lane & 3;
    const int warpM = wid & 1;     // 0..1 -> a offset 0/32
    const int warpN = wid >> 1;    // 0..3 -> c offset 0/32/64/96

    float accR[2][4][4] = {};      // [mi][ni][reg]
    float accI[2][4][4] = {};

    // prefetch k-tile 0
    uint2 ra[4], rb[8];
#pragma unroll
    for (int j = 0; j < 4; j++) {
        int e = tid + j * 256, i = e & 63, kk = e >> 6;
        ra[j] = P[(size_t)kk * 1024 + a0b + i];
    }
#pragma unroll
    for (int j = 0; j < 8; j++) {
        int e = tid + j * 256, i = e & 127, kk = e >> 7;
        rb[j] = P[(size_t)kk * 1024 + c0b + i];
    }

    for (int kt = 0; kt < 64; kt++) {
        uint2* bufA = smA + (kt & 1) * A_BUF;
        uint2* bufB = smB + (kt & 1) * B_BUF;
#pragma unroll
        for (int j = 0; j < 4; j++) {
            int e = tid + j * 256, i = e & 63, kk = e >> 6;
            bufA[kk * ASTR + i] = ra[j];
        }
#pragma unroll
        for (int j = 0; j < 8; j++) {
            int e = tid + j * 256, i = e & 127, kk = e >> 7;
            bufB[kk * BSTR + i] = rb[j];
        }
        __syncthreads();

        if (kt < 63) {
            int k0n = (kt + 1) * 16;
#pragma unroll
            for (int j = 0; j < 4; j++) {
                int e = tid + j * 256, i = e & 63, kk = e >> 6;
                ra[j] = P[(size_t)(k0n + kk) * 1024 + a0b + i];
            }
#pragma unroll
            for (int j = 0; j < 8; j++) {
                int e = tid + j * 256, i = e & 127, kk = e >> 7;
                rb[j] = P[(size_t)(k0n + kk) * 1024 + c0b + i];
            }
        }

        // ---- build A fragments: [mi][array 0=rHi 1=rLo 2=iHi 3=iLo][reg] ----
        uint32_t Af[2][4][4];
#pragma unroll
        for (int mi = 0; mi < 2; mi++) {
            int row0 = warpM * 32 + mi * 16 + g;
#pragma unroll
            for (int pos = 0; pos < 4; pos++) {
                int row = row0 + ((pos & 1) ? 8 : 0);
                int kk  = 2 * t4 + ((pos & 2) ? 8 : 0);
                uint2 e0 = bufA[kk * ASTR + row];
                uint2 e1 = bufA[(kk + 1) * ASTR + row];
                Af[mi][0][pos] = __byte_perm(e0.x, e1.x, 0x5410);
                Af[mi][1][pos] = __byte_perm(e0.x, e1.x, 0x7632);
                Af[mi][2][pos] = __byte_perm(e0.y, e1.y, 0x5410);
                Af[mi][3][pos] = __byte_perm(e0.y, e1.y, 0x7632);
            }
        }

#pragma unroll
        for (int ni = 0; ni < 4; ni++) {
            int col = warpN * 32 + ni * 8 + g;
            int kk = 2 * t4;
            uint2 e0 = bufB[kk * BSTR + col];
            uint2 e1 = bufB[(kk + 1) * BSTR + col];
            uint2 e2 = bufB[(kk + 8) * BSTR + col];
            uint2 e3 = bufB[(kk + 9) * BSTR + col];
            uint32_t BrH[2], BrL[2], BiH[2], BiL[2], BnH[2], BnL[2];
            BrH[0] = __byte_perm(e0.x, e1.x, 0x5410);
            BrL[0] = __byte_perm(e0.x, e1.x, 0x7632);
            BiH[0] = __byte_perm(e0.y, e1.y, 0x5410);
            BiL[0] = __byte_perm(e0.y, e1.y, 0x7632);
            BrH[1] = __byte_perm(e2.x, e3.x, 0x5410);
            BrL[1] = __byte_perm(e2.x, e3.x, 0x7632);
            BiH[1] = __byte_perm(e2.y, e3.y, 0x5410);
            BiL[1] = __byte_perm(e2.y, e3.y, 0x7632);
            BnH[0] = BiH[0] ^ 0x80008000u;
            BnL[0] = BiL[0] ^ 0x80008000u;
            BnH[1] = BiH[1] ^ 0x80008000u;
            BnL[1] = BiL[1] ^ 0x80008000u;
#pragma unroll
            for (int mi = 0; mi < 2; mi++) {
                float* dR = accR[mi][ni];
                float* dI = accI[mi][ni];
                // Real: Ar*Br + Ai*Bi, each 3 split terms
                mma_bf16(dR, Af[mi][0][0], Af[mi][0][1], Af[mi][0][2], Af[mi][0][3], BrH[0], BrH[1]);
                mma_bf16(dR, Af[mi][0][0], Af[mi][0][1], Af[mi][0][2], Af[mi][0][3], BrL[0], BrL[1]);
                mma_bf16(dR, Af[mi][1][0], Af[mi][1][1], Af[mi][1][2], Af[mi][1][3], BrH[0], BrH[1]);
                mma_bf16(dR, Af[mi][2][0], Af[mi][2][1], Af[mi][2][2], Af[mi][2][3], BiH[0], BiH[1]);
                mma_bf16(dR, Af[mi][2][0], Af[mi][2][1], Af[mi][2][2], Af[mi][2][3], BiL[0], BiL[1]);
                mma_bf16(dR, Af[mi][3][0], Af[mi][3][1], Af[mi][3][2], Af[mi][3][3], BiH[0], BiH[1]);
                // Imag: Ai*Br + Ar*(-Bi)
                mma_bf16(dI, Af[mi][2][0], Af[mi][2][1], Af[mi][2][2], Af[mi][2][3], BrH[0], BrH[1]);
                mma_bf16(dI, Af[mi][2][0], Af[mi][2][1], Af[mi][2][2], Af[mi][2][3], BrL[0], BrL[1]);
                mma_bf16(dI, Af[mi][3][0], Af[mi][3][1], Af[mi][3][2], Af[mi][3][3], BrH[0], BrH[1]);
                mma_bf16(dI, Af[mi][0][0], Af[mi][0][1], Af[mi][0][2], Af[mi][0][3], BnH[0], BnH[1]);
                mma_bf16(dI, Af[mi][0][0], Af[mi][0][1], Af[mi][0][2], Af[mi][0][3], BnL[0], BnL[1]);
                mma_bf16(dI, Af[mi][1][0], Af[mi][1][1], Af[mi][1][2], Af[mi][1][3], BnH[0], BnH[1]);
            }
        }
        __syncthreads();
    }

    // ---- epilogue: exactly-once writes via per-element guards ----
    float2* out2 = (float2*)out;
#pragma unroll
    for (int mi = 0; mi < 2; mi++)
#pragma unroll
        for (int ni = 0; ni < 4; ni++)
#pragma unroll
            for (int r = 0; r < 4; r++) {
                int a = a0b + warpM * 32 + mi * 16 + g + ((r & 2) ? 8 : 0);
                int c = c0b + warpN * 32 + ni * 8 + 2 * t4 + (r & 1);
                float vr = accR[mi][ni][r];
                float vi = accI[mi][ni][r];
                if (a <= c)
                    out2[(size_t)(b * 1024 + a) * 1024 + c] = make_float2(vr, vi);
                if (a < c)
                    out2[(size_t)(b * 1024 + c) * 1024 + a] = make_float2(vr, -vi);
            }
}

// ---------------- launch ----------------
extern "C" void kernel_launch(void* const* d_in, const int* in_sizes, int n_in,
                              void* d_out, int out_size) {
    const float* x = (const float*)d_in[0];
    const float* w = (const float*)d_in[1];
    float* out = (float*)d_out;

    cudaFuncSetAttribute(rdm_gemm, cudaFuncAttributeMaxDynamicSharedMemorySize, GEMM_SMEM);

    precompute_gates<<<1, 32>>>(w);
    pass_high<<<dim3(1024 / LOWC, BATCH), 256>>>(x);
    pass_low<<<dim3(512, BATCH), 256>>>();
    rdm_gemm<<<dim3(72, BATCH), 256, GEMM_SMEM>>>(out);
}